// round 12
// baseline (speedup 1.0000x reference)
#include <cuda_runtime.h>
#include <cuda_bf16.h>
#include <cstdint>

#define B_  4
#define H_  8
#define LQ_ 256
#define LK_ 256
#define DK_ 64
#define BH_ (B_*H_)                 // 32
#define NQROWS (BH_*LQ_)            // 8192
#define NKROWS (BH_*LK_)            // 8192
#define LOG2E 1.4426950408889634f

typedef unsigned long long ull;

// Projected q,k as f16x2 words: row r (0..16383), 32 words (64 dims).
__device__ uint32_t g_ph[(NQROWS + NKROWS) * 32];   // 2 MB

// ---------------- packed-math helpers -------------------------------------
// f16x2 pack: first PTX operand -> HIGH half
__device__ __forceinline__ uint32_t cvt_h2(float hi, float lo) {
    uint32_t r; asm("cvt.rn.f16x2.f32 %0,%1,%2;" : "=r"(r) : "f"(hi), "f"(lo)); return r;
}
__device__ __forceinline__ uint32_t hadd2(uint32_t a, uint32_t b) {
    uint32_t r; asm("add.rn.f16x2 %0,%1,%2;" : "=r"(r) : "r"(a), "r"(b)); return r;
}
__device__ __forceinline__ uint32_t hfma2(uint32_t a, uint32_t b, uint32_t c) {
    uint32_t r; asm("fma.rn.f16x2 %0,%1,%2,%3;" : "=r"(r) : "r"(a), "r"(b), "r"(c)); return r;
}
__device__ __forceinline__ uint32_t tanh2(uint32_t x) {
    uint32_t y; asm("tanh.approx.f16x2 %0,%1;" : "=r"(y) : "r"(x)); return y;
}
__device__ __forceinline__ void h2tof(uint32_t h, float& lo, float& hi) {
    asm("{.reg .b16 l,h; mov.b32 {l,h},%2; cvt.f32.f16 %0,l; cvt.f32.f16 %1,h;}"
        : "=f"(lo), "=f"(hi) : "r"(h));
}
__device__ __forceinline__ float ex2_fast(float x) {
    float y; asm("ex2.approx.f32 %0,%1;" : "=f"(y) : "f"(x)); return y;
}
__device__ __forceinline__ uint32_t smem_u32(const void* p) {
    return (uint32_t)__cvta_generic_to_shared(p);
}

// ---------------------------------------------------------------------------
// Kernel 1: projections via HMMA. grid 256 CTAs x 128 thr (4 warps).
// ---------------------------------------------------------------------------
__global__ __launch_bounds__(128) void proj_kernel(
    const float* __restrict__ q, const float* __restrict__ k,
    const float* __restrict__ Wq, const float* __restrict__ bq,
    const float* __restrict__ Wk, const float* __restrict__ bk)
{
    __shared__ uint32_t xs[64 * 36];   // x f16, 64 rows, pitch 72 f16
    __shared__ uint32_t ws[64 * 36];   // W^T f16: row d, cols e
    __shared__ float bs[64];
    const int tid  = threadIdx.x;
    const int wid  = tid >> 5;
    const int lane = tid & 31;
    const bool isK = (blockIdx.x >= 128);
    const float* W    = isK ? Wk : Wq;
    const float* bias = isK ? bk : bq;
    const int rowbase = (blockIdx.x & 127) * 64;
    const float* src  = (isK ? k : q) + (size_t)rowbase * 64;

    for (int i = tid; i < 2048; i += 128) {
        const int row = i >> 5, j = i & 31;
        float2 t = *(const float2*)(src + row * 64 + 2 * j);
        xs[row * 36 + j] = cvt_h2(t.y, t.x);
    }
    for (int i = tid; i < 2048; i += 128) {
        const int d = i >> 5, j = i & 31;
        ws[d * 36 + j] = cvt_h2(W[(2 * j + 1) * 64 + d], W[(2 * j) * 64 + d]);
    }
    if (tid < 64) bs[tid] = bias[tid];
    __syncthreads();

    uint32_t a[4][4];
    {
        const uint32_t abase = smem_u32(xs) + ((wid * 16 + (lane & 15)) * 36) * 4;
#pragma unroll
        for (int ks = 0; ks < 4; ks++) {
            const uint32_t pa = abase + (ks * 8 + (lane >> 4) * 4) * 4;
            asm volatile("ldmatrix.sync.aligned.m8n8.x4.shared.b16 {%0,%1,%2,%3}, [%4];"
                         : "=r"(a[ks][0]), "=r"(a[ks][1]), "=r"(a[ks][2]), "=r"(a[ks][3])
                         : "r"(pa));
        }
    }

    const int qr = lane >> 2;
    const int cb = 2 * (lane & 3);
    const int rowg = (isK ? NQROWS : 0) + rowbase + wid * 16 + qr;
#pragma unroll
    for (int n = 0; n < 8; n++) {
        float c0 = 0.f, c1 = 0.f, c2 = 0.f, c3 = 0.f;
#pragma unroll
        for (int ks = 0; ks < 4; ks++) {
            uint32_t b0, b1;
            const uint32_t vb = smem_u32(ws) + ((ks * 16 + (lane & 15)) * 36 + n * 4) * 4;
            asm volatile("ldmatrix.sync.aligned.m8n8.x2.trans.shared.b16 {%0,%1}, [%2];"
                         : "=r"(b0), "=r"(b1) : "r"(vb));
            asm volatile("mma.sync.aligned.m16n8k16.row.col.f32.f16.f16.f32 "
                         "{%0,%1,%2,%3},{%4,%5,%6,%7},{%8,%9},{%0,%1,%2,%3};"
                         : "+f"(c0), "+f"(c1), "+f"(c2), "+f"(c3)
                         : "r"(a[ks][0]), "r"(a[ks][1]), "r"(a[ks][2]), "r"(a[ks][3]),
                           "r"(b0), "r"(b1));
        }
        const int col = n * 8 + cb;
        const float blo = bs[col], bhi = bs[col + 1];
        g_ph[(size_t)rowg * 32 + n * 4 + (lane & 3)] =
            cvt_h2(c1 + bhi, c0 + blo);
        g_ph[(size_t)(rowg + 8) * 32 + n * 4 + (lane & 3)] =
            cvt_h2(c3 + bhi, c2 + blo);
    }
}

// ---------------------------------------------------------------------------
// Kernel 2: fused additive attention, 8-row q-tiles for load balance.
// grid = 1024 CTAs (32 bh x 32 q-tiles of 8 rows), 256 thr, 4 CTAs/SM.
// lane: q = lane&7, kg = lane>>3; warp wid covers k in [32w,32w+32),
// lane covers 8 k's [32w+8kg, +8).
// ---------------------------------------------------------------------------
// smem layout (u32 word indices)
#define SM_KV    0         // 9216 (kp f16x2 pitch 32; later v f16 pitch 36w)
#define SM_W2H   9216      // 32
#define SM_S     9248      // 2304 f32 scores pitch 9; overlays p_h (16x132)
#define SM_PMAX  11552     // 8 x 36
#define SM_PSUM  11840     // 8 x 36
#define SM_M     12128     // 8
#define SM_R     12136     // 8
#define SM_WORDS 12144     // 48576 bytes

#define P_PITCH_W 132      // p_h pitch in u32 words (264 f16, 528B)
#define V_PITCH_W 36       // v_h pitch in u32 words (72 f16, 144B)

__global__ __launch_bounds__(256, 4) void attn_kernel(
    const float* __restrict__ v,
    const float* __restrict__ vs_w,
    float* __restrict__ out,        // [BH,256,64]
    float* __restrict__ attn_out)   // [BH,256,256]
{
    extern __shared__ float sm[];
    uint32_t* kv_u  = (uint32_t*)sm + SM_KV;
    uint32_t* w2h_s = (uint32_t*)sm + SM_W2H;
    float*    s_s   = sm + SM_S;
    uint32_t* ph_u  = (uint32_t*)sm + SM_S;   // overlays s_s after scores die
    float* pmax = sm + SM_PMAX;
    float* psum = sm + SM_PSUM;
    float* m_s  = sm + SM_M;
    float* r_s  = sm + SM_R;

    const int tid  = threadIdx.x;
    const int wid  = tid >> 5;
    const int lane = tid & 31;
    const int bh   = blockIdx.x >> 5;
    const int qt   = blockIdx.x & 31;

    // ---- phase 0: stage kp (f16x2, pitch 32 words) + w --------------------
    {
        const uint4* src = (const uint4*)(g_ph + (size_t)(NQROWS + bh * LK_) * 32);
        uint4* dst = (uint4*)kv_u;
#pragma unroll
        for (int i = 0; i < 8; i++) dst[tid + 256 * i] = src[tid + 256 * i];
    }
    if (tid < 32) w2h_s[tid] = cvt_h2(vs_w[2 * tid + 1], vs_w[2 * tid]);
    __syncthreads();

    // ---- phase 1: scores ---------------------------------------------------
    const int q     = lane & 7;
    const int kg    = lane >> 3;
    const int kbase = wid * 32 + kg * 8;
    const int qrow  = bh * LQ_ + qt * 8 + q;
    float cm = -1e30f;

#pragma unroll 1
    for (int h = 0; h < 2; h++) {
        uint32_t qph[16], wh[16];
        {
            const uint4* qs = (const uint4*)(g_ph + (size_t)qrow * 32 + h * 16);
#pragma unroll
            for (int j = 0; j < 4; j++) {
                uint4 t = qs[j];
                qph[4*j] = t.x; qph[4*j+1] = t.y; qph[4*j+2] = t.z; qph[4*j+3] = t.w;
            }
        }
#pragma unroll
        for (int j = 0; j < 16; j++) wh[j] = w2h_s[h * 16 + j];

        const uint4* kr = (const uint4*)(kv_u + kbase * 32 + h * 16);
        float* srow = s_s + kbase * 9 + q;
#pragma unroll 2
        for (int kk = 0; kk < 8; kk++, kr += 8, srow += 9) {
            const uint4 c0 = kr[0], c1 = kr[1], c2 = kr[2], c3 = kr[3];
            uint32_t h0 = 0, h1 = 0, g0 = 0, g1 = 0;
            h0 = hfma2(tanh2(hadd2(qph[0],  c0.x)), wh[0],  h0);
            h1 = hfma2(tanh2(hadd2(qph[1],  c0.y)), wh[1],  h1);
            h0 = hfma2(tanh2(hadd2(qph[2],  c0.z)), wh[2],  h0);
            h1 = hfma2(tanh2(hadd2(qph[3],  c0.w)), wh[3],  h1);
            h0 = hfma2(tanh2(hadd2(qph[4],  c1.x)), wh[4],  h0);
            h1 = hfma2(tanh2(hadd2(qph[5],  c1.y)), wh[5],  h1);
            h0 = hfma2(tanh2(hadd2(qph[6],  c1.z)), wh[6],  h0);
            h1 = hfma2(tanh2(hadd2(qph[7],  c1.w)), wh[7],  h1);
            g0 = hfma2(tanh2(hadd2(qph[8],  c2.x)), wh[8],  g0);
            g1 = hfma2(tanh2(hadd2(qph[9],  c2.y)), wh[9],  g1);
            g0 = hfma2(tanh2(hadd2(qph[10], c2.z)), wh[10], g0);
            g1 = hfma2(tanh2(hadd2(qph[11], c2.w)), wh[11], g1);
            g0 = hfma2(tanh2(hadd2(qph[12], c3.x)), wh[12], g0);
            g1 = hfma2(tanh2(hadd2(qph[13], c3.y)), wh[13], g1);
            g0 = hfma2(tanh2(hadd2(qph[14], c3.z)), wh[14], g0);
            g1 = hfma2(tanh2(hadd2(qph[15], c3.w)), wh[15], g1);
            const uint32_t hs = hadd2(h0, h1);
            const uint32_t gs = hadd2(g0, g1);
            float f0, f1, f2, f3;
            h2tof(hs, f0, f1); h2tof(gs, f2, f3);
            const float part = (f0 + f1) + (f2 + f3);

            if (h == 0) {
                *srow = part;
            } else {
                const float sc = *srow + part;
                *srow = sc;
                cm = fmaxf(cm, sc);
            }
        }
    }
    pmax[q * 36 + wid * 4 + kg] = cm;
    __syncthreads();

    // ---- phase 2: row max + stage v as f16 (pitch 72 f16, overwrites kp) --
    if (tid < 8) {
        float m = pmax[tid * 36];
#pragma unroll
        for (int i = 1; i < 32; i++) m = fmaxf(m, pmax[tid * 36 + i]);
        m_s[tid] = m;
    }
    {
        const float4* vsrc = (const float4*)(v + (size_t)bh * (LK_ * DK_));
#pragma unroll
        for (int i = 0; i < 16; i++) {
            const int idx = tid + 256 * i;           // 0..4095; k=idx>>4, c=idx&15
            float4 t = vsrc[idx];
            const int kk2 = idx >> 4, c = idx & 15;
            uint32_t w0 = cvt_h2(t.y, t.x);
            uint32_t w1 = cvt_h2(t.w, t.z);
            *(uint2*)(kv_u + kk2 * V_PITCH_W + 2 * c) = make_uint2(w0, w1);
        }
    }
    __syncthreads();

    // ---- phase 3: exp into registers, partial sums -------------------------
    const int qe  = tid & 7;
    const int grp = tid >> 3;          // 0..31, covers k in [8*grp, 8*grp+8)
    float e[8];
    {
        const float m = m_s[qe];
        float s = 0.f;
#pragma unroll
        for (int kk = 0; kk < 8; kk++) {
            const int k = grp * 8 + kk;
            const float ev = ex2_fast((s_s[k * 9 + qe] - m) * LOG2E);
            e[kk] = ev;
            s += ev;
        }
        psum[qe * 36 + grp] = s;
    }
    __syncthreads();
    if (tid < 8) {
        float l = psum[tid * 36];
#pragma unroll
        for (int i = 1; i < 32; i++) l += psum[tid * 36 + i];
        r_s[tid] = 1.0f / l;
    }
    __syncthreads();

    // ---- phase 4: write attn (from regs) + p_h f16 (overlays s_s) ---------
    {
        const float r = r_s[qe];
        float4* ab = (float4*)(attn_out + (size_t)(bh * LQ_ + qt * 8 + qe) * LK_
                               + grp * 8);
        ab[0] = make_float4(e[0] * r, e[1] * r, e[2] * r, e[3] * r);
        ab[1] = make_float4(e[4] * r, e[5] * r, e[6] * r, e[7] * r);
#pragma unroll
        for (int j = 0; j < 4; j++)
            ph_u[qe * P_PITCH_W + grp * 4 + j] = cvt_h2(e[2*j+1] * r, e[2*j] * r);
        // zero pad rows 8..15 of p_h (A-matrix padding for m16n8k16)
#pragma unroll
        for (int j = 0; j < 4; j++)
            ph_u[(8 + qe) * P_PITCH_W + grp * 4 + j] = 0u;
    }
    __syncthreads();

    // ---- phase 5: epilogue GEMM out[8q x 64d] = p[8x256] @ v[256x64] ------
    // (A padded to 16 rows with zeros; rows 8..15 of C discarded)
    {
        const int d0 = wid * 8;
        float c0 = 0.f, c1 = 0.f, c2 = 0.f, c3 = 0.f;
        const uint32_t pa_base = smem_u32(ph_u) + ((lane & 15) * P_PITCH_W) * 4;
        const uint32_t vb_base = smem_u32(kv_u) + ((lane & 15) * V_PITCH_W + (d0 >> 1)) * 4;
#pragma unroll
        for (int kb = 0; kb < 16; kb++) {
            uint32_t a0, a1, a2, a3, b0, b1;
            const uint32_t pa = pa_base + (kb * 8 + (lane >> 4) * 4) * 4;
            asm volatile("ldmatrix.sync.aligned.m8n8.x4.shared.b16 {%0,%1,%2,%3}, [%4];"
                         : "=r"(a0), "=r"(a1), "=r"(a2), "=r"(a3) : "r"(pa));
            const uint32_t vb = vb_base + (kb * 16 * V_PITCH_W) * 4;
            asm volatile("ldmatrix.sync.aligned.m8n8.x2.trans.shared.b16 {%0,%1}, [%2];"
                         : "=r"(b0), "=r"(b1) : "r"(vb));
            asm volatile("mma.sync.aligned.m16n8k16.row.col.f32.f16.f16.f32 "
                         "{%0,%1,%2,%3},{%4,%5,%6,%7},{%8,%9},{%0,%1,%2,%3};"
                         : "+f"(c0), "+f"(c1), "+f"(c2), "+f"(c3)
                         : "r"(a0), "r"(a1), "r"(a2), "r"(a3), "r"(b0), "r"(b1));
        }
        const int qr = lane >> 2;      // 0..7 (real rows)
        const int dc = d0 + 2 * (lane & 3);
        float* ob = out + (size_t)(bh * LQ_ + qt * 8) * DK_;
        *(float2*)(ob + qr * DK_ + dc) = make_float2(c0, c1);
        // c2,c3 correspond to padded rows 8..15: discarded
    }
}

// ---------------------------------------------------------------------------
extern "C" void kernel_launch(void* const* d_in, const int* in_sizes, int n_in,
                              void* d_out, int out_size)
{
    const float* q    = (const float*)d_in[0];
    const float* k    = (const float*)d_in[1];
    const float* v    = (const float*)d_in[2];
    const float* Wq_w = (const float*)d_in[3];
    const float* Wq_b = (const float*)d_in[4];
    const float* Wk_w = (const float*)d_in[5];
    const float* Wk_b = (const float*)d_in[6];
    const float* vs_w = (const float*)d_in[7];
    // vs_b (d_in[8]) is softmax-invariant: unused.

    float* out  = (float*)d_out;                            // [B,H,LQ,DK]
    float* attn = (float*)d_out + (size_t)BH_ * LQ_ * DK_;  // [B,H,LQ,LK]

    const int smem_bytes = SM_WORDS * 4;
    cudaFuncSetAttribute(attn_kernel, cudaFuncAttributeMaxDynamicSharedMemorySize,
                         smem_bytes);

    proj_kernel<<<256, 128>>>(q, k, Wq_w, Wq_b, Wk_w, Wk_b);
    attn_kernel<<<1024, 256, smem_bytes>>>(v, vs_w, out, attn);
}

// round 13
// speedup vs baseline: 1.4191x; 1.4191x over previous
#include <cuda_runtime.h>
#include <cuda_bf16.h>
#include <cstdint>

#define B_  4
#define H_  8
#define LQ_ 256
#define LK_ 256
#define DK_ 64
#define BH_ (B_*H_)                 // 32
#define NQROWS (BH_*LQ_)            // 8192
#define NKROWS (BH_*LK_)            // 8192
#define LOG2E 1.4426950408889634f

typedef unsigned long long ull;

// Projected q,k as f16x2 words: row r (0..16383), 32 words (64 dims).
__device__ uint32_t g_ph[(NQROWS + NKROWS) * 32];   // 2 MB

// ---------------- packed-math helpers -------------------------------------
// f16x2 pack: first PTX operand -> HIGH half
__device__ __forceinline__ uint32_t cvt_h2(float hi, float lo) {
    uint32_t r; asm("cvt.rn.f16x2.f32 %0,%1,%2;" : "=r"(r) : "f"(hi), "f"(lo)); return r;
}
__device__ __forceinline__ uint32_t hadd2(uint32_t a, uint32_t b) {
    uint32_t r; asm("add.rn.f16x2 %0,%1,%2;" : "=r"(r) : "r"(a), "r"(b)); return r;
}
__device__ __forceinline__ uint32_t hfma2(uint32_t a, uint32_t b, uint32_t c) {
    uint32_t r; asm("fma.rn.f16x2 %0,%1,%2,%3;" : "=r"(r) : "r"(a), "r"(b), "r"(c)); return r;
}
__device__ __forceinline__ uint32_t tanh2(uint32_t x) {
    uint32_t y; asm("tanh.approx.f16x2 %0,%1;" : "=r"(y) : "r"(x)); return y;
}
__device__ __forceinline__ void h2tof(uint32_t h, float& lo, float& hi) {
    asm("{.reg .b16 l,h; mov.b32 {l,h},%2; cvt.f32.f16 %0,l; cvt.f32.f16 %1,h;}"
        : "=f"(lo), "=f"(hi) : "r"(h));
}
__device__ __forceinline__ float ex2_fast(float x) {
    float y; asm("ex2.approx.f32 %0,%1;" : "=f"(y) : "f"(x)); return y;
}
__device__ __forceinline__ uint32_t smem_u32(const void* p) {
    return (uint32_t)__cvta_generic_to_shared(p);
}

// ---------------------------------------------------------------------------
// Kernel 1: projections via HMMA. grid 256 CTAs x 128 thr (4 warps).
// ---------------------------------------------------------------------------
__global__ __launch_bounds__(128) void proj_kernel(
    const float* __restrict__ q, const float* __restrict__ k,
    const float* __restrict__ Wq, const float* __restrict__ bq,
    const float* __restrict__ Wk, const float* __restrict__ bk)
{
    __shared__ uint32_t xs[64 * 36];   // x f16, 64 rows, pitch 72 f16
    __shared__ uint32_t ws[64 * 36];   // W^T f16: row d, cols e
    __shared__ float bs[64];
    const int tid  = threadIdx.x;
    const int wid  = tid >> 5;
    const int lane = tid & 31;
    const bool isK = (blockIdx.x >= 128);
    const float* W    = isK ? Wk : Wq;
    const float* bias = isK ? bk : bq;
    const int rowbase = (blockIdx.x & 127) * 64;
    const float* src  = (isK ? k : q) + (size_t)rowbase * 64;

    for (int i = tid; i < 2048; i += 128) {
        const int row = i >> 5, j = i & 31;
        float2 t = *(const float2*)(src + row * 64 + 2 * j);
        xs[row * 36 + j] = cvt_h2(t.y, t.x);
    }
    for (int i = tid; i < 2048; i += 128) {
        const int d = i >> 5, j = i & 31;
        ws[d * 36 + j] = cvt_h2(W[(2 * j + 1) * 64 + d], W[(2 * j) * 64 + d]);
    }
    if (tid < 64) bs[tid] = bias[tid];
    __syncthreads();

    uint32_t a[4][4];
    {
        const uint32_t abase = smem_u32(xs) + ((wid * 16 + (lane & 15)) * 36) * 4;
#pragma unroll
        for (int ks = 0; ks < 4; ks++) {
            const uint32_t pa = abase + (ks * 8 + (lane >> 4) * 4) * 4;
            asm volatile("ldmatrix.sync.aligned.m8n8.x4.shared.b16 {%0,%1,%2,%3}, [%4];"
                         : "=r"(a[ks][0]), "=r"(a[ks][1]), "=r"(a[ks][2]), "=r"(a[ks][3])
                         : "r"(pa));
        }
    }

    const int qr = lane >> 2;
    const int cb = 2 * (lane & 3);
    const int rowg = (isK ? NQROWS : 0) + rowbase + wid * 16 + qr;
#pragma unroll
    for (int n = 0; n < 8; n++) {
        float c0 = 0.f, c1 = 0.f, c2 = 0.f, c3 = 0.f;
#pragma unroll
        for (int ks = 0; ks < 4; ks++) {
            uint32_t b0, b1;
            const uint32_t vb = smem_u32(ws) + ((ks * 16 + (lane & 15)) * 36 + n * 4) * 4;
            asm volatile("ldmatrix.sync.aligned.m8n8.x2.trans.shared.b16 {%0,%1}, [%2];"
                         : "=r"(b0), "=r"(b1) : "r"(vb));
            asm volatile("mma.sync.aligned.m16n8k16.row.col.f32.f16.f16.f32 "
                         "{%0,%1,%2,%3},{%4,%5,%6,%7},{%8,%9},{%0,%1,%2,%3};"
                         : "+f"(c0), "+f"(c1), "+f"(c2), "+f"(c3)
                         : "r"(a[ks][0]), "r"(a[ks][1]), "r"(a[ks][2]), "r"(a[ks][3]),
                           "r"(b0), "r"(b1));
        }
        const int col = n * 8 + cb;
        const float blo = bs[col], bhi = bs[col + 1];
        g_ph[(size_t)rowg * 32 + n * 4 + (lane & 3)] =
            cvt_h2(c1 + bhi, c0 + blo);
        g_ph[(size_t)(rowg + 8) * 32 + n * 4 + (lane & 3)] =
            cvt_h2(c3 + bhi, c2 + blo);
    }
}

// ---------------------------------------------------------------------------
// Kernel 2: fused additive attention (R9 structure, kp read from L2,
// v staged up-front so mid-kernel bubbles shrink).
// grid = 512 CTAs (32 bh x 16 q-tiles of 16 rows), 256 thr, 4 CTAs/SM.
// ---------------------------------------------------------------------------
// smem layout (u32 word indices)
#define SM_KV    0        // 9216 (v f16, pitch 36 words) — staged in phase 0
#define SM_W2H   9216     // 32
#define SM_S     9248     // 4352 f32 scores pitch 17; later p_h f16 pitch 264
#define SM_PMAX  13600    // 16 x 17
#define SM_PSUM  13872    // 16 x 17
#define SM_M     14144    // 16
#define SM_R     14160    // 16
#define SM_WORDS 14176    // 56704 bytes

#define P_PITCH_W 132     // p_h pitch in u32 words (264 f16, 528B)
#define V_PITCH_W 36      // v_h pitch in u32 words (72 f16, 144B)

__global__ __launch_bounds__(256, 4) void attn_kernel(
    const float* __restrict__ v,
    const float* __restrict__ vs_w,
    float* __restrict__ out,        // [BH,256,64]
    float* __restrict__ attn_out)   // [BH,256,256]
{
    extern __shared__ float sm[];
    uint32_t* kv_u  = (uint32_t*)sm + SM_KV;
    uint32_t* w2h_s = (uint32_t*)sm + SM_W2H;
    float*    s_s   = sm + SM_S;
    uint32_t* ph_u  = (uint32_t*)sm + SM_S;   // overlays s_s after scores die
    float* pmax = sm + SM_PMAX;
    float* psum = sm + SM_PSUM;
    float* m_s  = sm + SM_M;
    float* r_s  = sm + SM_R;

    const int tid  = threadIdx.x;
    const int wid  = tid >> 5;
    const int lane = tid & 31;
    const int bh   = blockIdx.x >> 4;
    const int qt   = blockIdx.x & 15;

    // ---- phase 0: stage v as f16 (pitch 72 f16) + w -----------------------
    // (v depends on nothing; kp is NOT staged — main loop reads it from L2)
    {
        const float4* vsrc = (const float4*)(v + (size_t)bh * (LK_ * DK_));
#pragma unroll
        for (int i = 0; i < 16; i++) {
            const int idx = tid + 256 * i;           // 0..4095; k=idx>>4, c=idx&15
            float4 t = vsrc[idx];
            const int kk2 = idx >> 4, c = idx & 15;
            uint32_t w0 = cvt_h2(t.y, t.x);
            uint32_t w1 = cvt_h2(t.w, t.z);
            *(uint2*)(kv_u + kk2 * V_PITCH_W + 2 * c) = make_uint2(w0, w1);
        }
    }
    if (tid < 32) w2h_s[tid] = cvt_h2(vs_w[2 * tid + 1], vs_w[2 * tid]);
    // no barrier needed before phase 1 (phase 1 touches only s_s + w2h_s).
    __syncthreads();   // covers w2h_s visibility; v region not read until phase 5

    // ---- phase 1: scores (kp streamed from L2) ----------------------------
    const int q    = lane & 15;
    const int kh   = lane >> 4;
    const int kbase = wid * 32 + kh * 16;
    const int qrow = bh * LQ_ + qt * 16 + q;
    float cm = -1e30f;

#pragma unroll 1
    for (int h = 0; h < 2; h++) {
        uint32_t qph[16], wh[16];
        {
            const uint4* qs = (const uint4*)(g_ph + (size_t)qrow * 32 + h * 16);
#pragma unroll
            for (int j = 0; j < 4; j++) {
                uint4 t = qs[j];
                qph[4*j] = t.x; qph[4*j+1] = t.y; qph[4*j+2] = t.z; qph[4*j+3] = t.w;
            }
        }
#pragma unroll
        for (int j = 0; j < 16; j++) wh[j] = w2h_s[h * 16 + j];

        const uint4* kr = (const uint4*)(g_ph + (size_t)(NQROWS + bh * LK_ + kbase) * 32
                                         + h * 16);
        float* srow = s_s + kbase * 17 + q;
#pragma unroll 2
        for (int kk = 0; kk < 16; kk++, kr += 8, srow += 17) {
            const uint4 c0 = kr[0], c1 = kr[1], c2 = kr[2], c3 = kr[3];
            uint32_t h0 = 0, h1 = 0, g0 = 0, g1 = 0;
            h0 = hfma2(tanh2(hadd2(qph[0],  c0.x)), wh[0],  h0);
            h1 = hfma2(tanh2(hadd2(qph[1],  c0.y)), wh[1],  h1);
            h0 = hfma2(tanh2(hadd2(qph[2],  c0.z)), wh[2],  h0);
            h1 = hfma2(tanh2(hadd2(qph[3],  c0.w)), wh[3],  h1);
            h0 = hfma2(tanh2(hadd2(qph[4],  c1.x)), wh[4],  h0);
            h1 = hfma2(tanh2(hadd2(qph[5],  c1.y)), wh[5],  h1);
            h0 = hfma2(tanh2(hadd2(qph[6],  c1.z)), wh[6],  h0);
            h1 = hfma2(tanh2(hadd2(qph[7],  c1.w)), wh[7],  h1);
            g0 = hfma2(tanh2(hadd2(qph[8],  c2.x)), wh[8],  g0);
            g1 = hfma2(tanh2(hadd2(qph[9],  c2.y)), wh[9],  g1);
            g0 = hfma2(tanh2(hadd2(qph[10], c2.z)), wh[10], g0);
            g1 = hfma2(tanh2(hadd2(qph[11], c2.w)), wh[11], g1);
            g0 = hfma2(tanh2(hadd2(qph[12], c3.x)), wh[12], g0);
            g1 = hfma2(tanh2(hadd2(qph[13], c3.y)), wh[13], g1);
            g0 = hfma2(tanh2(hadd2(qph[14], c3.z)), wh[14], g0);
            g1 = hfma2(tanh2(hadd2(qph[15], c3.w)), wh[15], g1);
            const uint32_t hs = hadd2(h0, h1);
            const uint32_t gs = hadd2(g0, g1);
            float f0, f1, f2, f3;
            h2tof(hs, f0, f1); h2tof(gs, f2, f3);
            const float part = (f0 + f1) + (f2 + f3);

            if (h == 0) {
                *srow = part;
            } else {
                const float sc = *srow + part;
                *srow = sc;
                cm = fmaxf(cm, sc);
            }
        }
    }
    pmax[q * 17 + wid * 2 + kh] = cm;
    __syncthreads();

    // ---- phase 2: row max (tiny; v already staged) ------------------------
    if (tid < 16) {
        float m = pmax[tid * 17];
#pragma unroll
        for (int i = 1; i < 16; i++) m = fmaxf(m, pmax[tid * 17 + i]);
        m_s[tid] = m;
    }
    __syncthreads();

    // ---- phase 3: exp into registers, partial sums -------------------------
    const int qe = tid & 15;
    const int ks = tid >> 4;
    float e[16];
    {
        const float m = m_s[qe];
        float s = 0.f;
#pragma unroll
        for (int kk = 0; kk < 16; kk++) {
            const int k = ks * 16 + kk;
            const float ev = ex2_fast((s_s[k * 17 + qe] - m) * LOG2E);
            e[kk] = ev;
            s += ev;
        }
        psum[qe * 17 + ks] = s;
    }
    __syncthreads();
    if (tid < 16) {
        float l = psum[tid * 17];
#pragma unroll
        for (int i = 1; i < 16; i++) l += psum[tid * 17 + i];
        r_s[tid] = 1.0f / l;
    }
    __syncthreads();

    // ---- phase 4: write attn (from regs) + p_h f16 (overlays s_s) ---------
    {
        const float r = r_s[qe];
        float4* ab = (float4*)(attn_out + (size_t)(bh * LQ_ + qt * 16 + qe) * LK_
                               + ks * 16);
#pragma unroll
        for (int j = 0; j < 4; j++)
            ab[j] = make_float4(e[4*j] * r, e[4*j+1] * r, e[4*j+2] * r, e[4*j+3] * r);
#pragma unroll
        for (int j = 0; j < 8; j++)
            ph_u[qe * P_PITCH_W + ks * 8 + j] = cvt_h2(e[2*j+1] * r, e[2*j] * r);
    }
    __syncthreads();

    // ---- phase 5: epilogue GEMM out[16q x 64d] = p[16x256] @ v[256x64] ----
    {
        const int d0 = wid * 8;
        float c0 = 0.f, c1 = 0.f, c2 = 0.f, c3 = 0.f;
        const uint32_t pa_base = smem_u32(ph_u) + ((lane & 15) * P_PITCH_W) * 4;
        const uint32_t vb_base = smem_u32(kv_u) + ((lane & 15) * V_PITCH_W + (d0 >> 1)) * 4;
#pragma unroll
        for (int kb = 0; kb < 16; kb++) {
            uint32_t a0, a1, a2, a3, b0, b1;
            const uint32_t pa = pa_base + (kb * 8 + (lane >> 4) * 4) * 4;
            asm volatile("ldmatrix.sync.aligned.m8n8.x4.shared.b16 {%0,%1,%2,%3}, [%4];"
                         : "=r"(a0), "=r"(a1), "=r"(a2), "=r"(a3) : "r"(pa));
            const uint32_t vb = vb_base + (kb * 16 * V_PITCH_W) * 4;
            asm volatile("ldmatrix.sync.aligned.m8n8.x2.trans.shared.b16 {%0,%1}, [%2];"
                         : "=r"(b0), "=r"(b1) : "r"(vb));
            asm volatile("mma.sync.aligned.m16n8k16.row.col.f32.f16.f16.f32 "
                         "{%0,%1,%2,%3},{%4,%5,%6,%7},{%8,%9},{%0,%1,%2,%3};"
                         : "+f"(c0), "+f"(c1), "+f"(c2), "+f"(c3)
                         : "r"(a0), "r"(a1), "r"(a2), "r"(a3), "r"(b0), "r"(b1));
        }
        const int qr = lane >> 2;
        const int dc = d0 + 2 * (lane & 3);
        float* ob = out + (size_t)(bh * LQ_ + qt * 16) * DK_;
        *(float2*)(ob + qr * DK_ + dc)       = make_float2(c0, c1);
        *(float2*)(ob + (qr + 8) * DK_ + dc) = make_float2(c2, c3);
    }
}

// ---------------------------------------------------------------------------
extern "C" void kernel_launch(void* const* d_in, const int* in_sizes, int n_in,
                              void* d_out, int out_size)
{
    const float* q    = (const float*)d_in[0];
    const float* k    = (const float*)d_in[1];
    const float* v    = (const float*)d_in[2];
    const float* Wq_w = (const float*)d_in[3];
    const float* Wq_b = (const float*)d_in[4];
    const float* Wk_w = (const float*)d_in[5];
    const float* Wk_b = (const float*)d_in[6];
    const float* vs_w = (const float*)d_in[7];
    // vs_b (d_in[8]) is softmax-invariant: unused.

    float* out  = (float*)d_out;                            // [B,H,LQ,DK]
    float* attn = (float*)d_out + (size_t)BH_ * LQ_ * DK_;  // [B,H,LQ,LK]

    const int smem_bytes = SM_WORDS * 4;
    cudaFuncSetAttribute(attn_kernel, cudaFuncAttributeMaxDynamicSharedMemorySize,
                         smem_bytes);

    proj_kernel<<<256, 128>>>(q, k, Wq_w, Wq_b, Wk_w, Wk_b);
    attn_kernel<<<512, 256, smem_bytes>>>(v, vs_w, out, attn);
}